// round 2
// baseline (speedup 1.0000x reference)
#include <cuda_runtime.h>
#include <cuda_bf16.h>

#define NN 100000
#define NE 1600000
#define HF 64

// ---------------- scratch (device globals; no allocation allowed) ----------
__device__ float    g_h  [NN * HF];  // h = x@W for current layer
__device__ float    g_nf [NN * HF];  // node features after layer 1
__device__ float    g_nf2[NN * HF];  // node features after layer 2
__device__ float    g_e  [NE];       // edge logits, then exp() in-place
__device__ float    g_el [NN];
__device__ float    g_er [NN];
__device__ unsigned g_mk [NN];       // segment-max as order-preserving uint key
__device__ float    g_s  [NN];       // segment sum of exp

// Order-preserving float->uint key: monotone under unsigned compare.
__device__ __forceinline__ unsigned f2key(float f) {
    unsigned b = __float_as_uint(f);
    return b ^ ((unsigned)((int)b >> 31) | 0x80000000u);
}
__device__ __forceinline__ float key2f(unsigned k) {
    unsigned b = (k & 0x80000000u) ? (k ^ 0x80000000u) : ~k;
    return __uint_as_float(b);
}
// key(-inf): bits 0xFF800000 (negative) -> ~bits
#define KEY_NEG_INF 0x007FFFFFu

// ---------------- init: per-node max/sum + zero the output accumulator -----
__global__ void init_layer(unsigned* __restrict__ mk, float* __restrict__ s,
                           float* __restrict__ y) {
    int i = blockIdx.x * blockDim.x + threadIdx.x;
    if (i < NN) { mk[i] = KEY_NEG_INF; s[i] = 0.0f; }
    if (i < NN * HF) y[i] = 0.0f;
}

// ---------------- GEMM h = x@W, fused el = h.a_l, er = h.a_r ---------------
// One warp per node row. W [K][64] staged in shared. Lane computes cols
// (2*lane, 2*lane+1). Warp-reduce for el/er.
template <int K>
__global__ void __launch_bounds__(256)
gemm_el_er(const float* __restrict__ x, const float* __restrict__ W,
           const float* __restrict__ al, const float* __restrict__ ar,
           float* __restrict__ h, float* __restrict__ el, float* __restrict__ er) {
    __shared__ float sW[K * HF];
    __shared__ float sx[8][K];

    int tid = threadIdx.x;
    for (int i = tid; i < K * HF; i += 256) sW[i] = W[i];
    __syncthreads();

    int warp = tid >> 5, lane = tid & 31;
    int row = blockIdx.x * 8 + warp;
    if (row >= NN) return;

    #pragma unroll
    for (int i = lane; i < K; i += 32) sx[warp][i] = x[row * K + i];
    __syncwarp();

    int c = 2 * lane;
    float a0 = 0.0f, a1 = 0.0f;
    #pragma unroll 16
    for (int k = 0; k < K; k++) {
        float xv = sx[warp][k];
        float2 w2 = *(const float2*)&sW[k * HF + c];
        a0 = fmaf(xv, w2.x, a0);
        a1 = fmaf(xv, w2.y, a1);
    }
    *(float2*)&h[row * HF + c] = make_float2(a0, a1);

    float pel = a0 * al[c] + a1 * al[c + 1];
    float per = a0 * ar[c] + a1 * ar[c + 1];
    #pragma unroll
    for (int o = 16; o > 0; o >>= 1) {
        pel += __shfl_xor_sync(0xFFFFFFFFu, pel, o);
        per += __shfl_xor_sync(0xFFFFFFFFu, per, o);
    }
    if (lane == 0) { el[row] = pel; er[row] = per; }
}

// ---------------- edge pass 1: logits + segment max ------------------------
__global__ void edge_logits(const int* __restrict__ src, const int* __restrict__ dst,
                            const float* __restrict__ el, const float* __restrict__ er,
                            float* __restrict__ e, unsigned* __restrict__ mk) {
    int i = blockIdx.x * blockDim.x + threadIdx.x;
    if (i >= NE) return;
    int d = dst[i];
    float v = el[src[i]] + er[d];
    v = v > 0.0f ? v : 0.2f * v;   // leaky relu
    e[i] = v;
    atomicMax(&mk[d], f2key(v));
}

// ---------------- edge pass 2: exp + segment sum (in-place on e) -----------
__global__ void edge_exp(const int* __restrict__ dst, float* __restrict__ e,
                         const unsigned* __restrict__ mk, float* __restrict__ s) {
    int i = blockIdx.x * blockDim.x + threadIdx.x;
    if (i >= NE) return;
    int d = dst[i];
    float m = key2f(mk[d]);
    float ex = expf(e[i] - m);
    e[i] = ex;
    atomicAdd(&s[d], ex);
}

// ---------------- edge pass 3: weighted scatter-add ------------------------
// 16 threads per edge, 4 floats each (float4 gather of h[src]).
__global__ void __launch_bounds__(256)
edge_scatter(const int* __restrict__ src, const int* __restrict__ dst,
             const float* __restrict__ ex, const float* __restrict__ s,
             const float* __restrict__ h, float* __restrict__ y) {
    int gid = blockIdx.x * blockDim.x + threadIdx.x;
    int e = gid >> 4;
    if (e >= NE) return;
    int f  = (gid & 15) * 4;
    int sn = src[e];
    int dn = dst[e];
    float a = __fdividef(ex[e], s[dn]);
    float4 hv = *(const float4*)&h[sn * HF + f];
    float* yp = &y[dn * HF + f];
    atomicAdd(yp + 0, a * hv.x);
    atomicAdd(yp + 1, a * hv.y);
    atomicAdd(yp + 2, a * hv.z);
    atomicAdd(yp + 3, a * hv.w);
}

// ---------------- bias + relu ----------------------------------------------
__global__ void bias_relu(float* __restrict__ y, const float* __restrict__ b) {
    int i = blockIdx.x * blockDim.x + threadIdx.x;
    if (i >= NN * HF) return;
    float v = y[i] + b[i & (HF - 1)];
    y[i] = v > 0.0f ? v : 0.0f;
}

// ---------------- host-side layer driver -----------------------------------
// x and y must NOT alias (init_layer zeroes y before gemm reads x).
template <int K>
static void run_layer(const float* x, const float* W, const float* al,
                      const float* ar, const float* b,
                      const int* src, const int* dst,
                      float* h, float* e, float* el, float* er,
                      unsigned* mk, float* s, float* y) {
    init_layer<<<(NN * HF + 255) / 256, 256>>>(mk, s, y);
    gemm_el_er<K><<<(NN + 7) / 8, 256>>>(x, W, al, ar, h, el, er);
    edge_logits<<<(NE + 255) / 256, 256>>>(src, dst, el, er, e, mk);
    edge_exp<<<(NE + 255) / 256, 256>>>(dst, e, mk, s);
    edge_scatter<<<(NE * 16 + 255) / 256, 256>>>(src, dst, e, s, h, y);
    bias_relu<<<(NN * HF + 255) / 256, 256>>>(y, b);
}

extern "C" void kernel_launch(void* const* d_in, const int* in_sizes, int n_in,
                              void* d_out, int out_size) {
    const float* x   = (const float*)d_in[0];
    const int*   src = (const int*)  d_in[1];
    const int*   dst = (const int*)  d_in[2];
    const float* W1  = (const float*)d_in[3];
    const float* al1 = (const float*)d_in[4];
    const float* ar1 = (const float*)d_in[5];
    const float* b1  = (const float*)d_in[6];
    const float* W2  = (const float*)d_in[7];
    const float* al2 = (const float*)d_in[8];
    const float* ar2 = (const float*)d_in[9];
    const float* b2  = (const float*)d_in[10];
    const float* W3  = (const float*)d_in[11];
    const float* al3 = (const float*)d_in[12];
    const float* ar3 = (const float*)d_in[13];
    const float* b3  = (const float*)d_in[14];
    float* out = (float*)d_out;

    float *h, *nf, *nf2, *e, *el, *er, *s;
    unsigned* mk;
    cudaGetSymbolAddress((void**)&h,   g_h);
    cudaGetSymbolAddress((void**)&nf,  g_nf);
    cudaGetSymbolAddress((void**)&nf2, g_nf2);
    cudaGetSymbolAddress((void**)&e,   g_e);
    cudaGetSymbolAddress((void**)&el,  g_el);
    cudaGetSymbolAddress((void**)&er,  g_er);
    cudaGetSymbolAddress((void**)&mk,  g_mk);
    cudaGetSymbolAddress((void**)&s,   g_s);

    // layer 1: in_feat -> nf
    run_layer<128>(x,   W1, al1, ar1, b1, src, dst, h, e, el, er, mk, s, nf);
    // layer 2: nf -> nf2
    run_layer<64>(nf,  W2, al2, ar2, b2, src, dst, h, e, el, er, mk, s, nf2);
    // layer 3: nf2 -> d_out
    run_layer<64>(nf2, W3, al3, ar3, b3, src, dst, h, e, el, er, mk, s, out);
}

// round 3
// speedup vs baseline: 2.8669x; 2.8669x over previous
#include <cuda_runtime.h>
#include <cuda_bf16.h>

#define NN 100000
#define NE 1600000
#define HF 64
#define FULL 0xFFFFFFFFu

#define SB   512
#define NBLK ((NN + SB - 1) / SB)   // 196

// ---------------- scratch (device globals; no allocation allowed) ----------
__device__ float g_h  [NN * HF];   // h = x@W for current layer
__device__ float g_nf [NN * HF];   // node features after layer 1
__device__ float g_nf2[NN * HF];   // node features after layer 2
__device__ float g_el [NN];
__device__ float g_er [NN];
// CSR-by-dst
__device__ int g_cnt   [NN];
__device__ int g_incl  [NN];
__device__ int g_bsum  [NBLK];
__device__ int g_boff  [NBLK];
__device__ int g_rowptr[NN + 1];
__device__ int g_cursor[NN];
__device__ int g_csrc  [NE];       // src ids grouped by dst

// ============================ CSR build =====================================
__global__ void csr_zero(int* __restrict__ cnt) {
    int i = blockIdx.x * blockDim.x + threadIdx.x;
    if (i < NN) cnt[i] = 0;
}

__global__ void csr_hist(const int* __restrict__ dst, int* __restrict__ cnt) {
    int e = blockIdx.x * blockDim.x + threadIdx.x;
    if (e < NE) atomicAdd(&cnt[dst[e]], 1);
}

// per-block inclusive scan of 512 counts; write inclusive + block total
__global__ void csr_scan1(const int* __restrict__ cnt, int* __restrict__ incl,
                          int* __restrict__ bsum) {
    __shared__ int wsum[16];
    int tid = threadIdx.x, lane = tid & 31, wid = tid >> 5;
    int i = blockIdx.x * SB + tid;
    int v = (i < NN) ? cnt[i] : 0;
    int x = v;
    #pragma unroll
    for (int o = 1; o < 32; o <<= 1) {
        int t = __shfl_up_sync(FULL, x, o);
        if (lane >= o) x += t;
    }
    if (lane == 31) wsum[wid] = x;
    __syncthreads();
    if (wid == 0) {
        int w = (lane < 16) ? wsum[lane] : 0;
        #pragma unroll
        for (int o = 1; o < 16; o <<= 1) {
            int t = __shfl_up_sync(FULL, w, o);
            if (lane >= o) w += t;
        }
        if (lane < 16) wsum[lane] = w;
    }
    __syncthreads();
    int inc = x + (wid > 0 ? wsum[wid - 1] : 0);
    if (i < NN) incl[i] = inc;
    if (tid == SB - 1) bsum[blockIdx.x] = inc;
}

// single block: exclusive scan of the NBLK (<=256) block sums
__global__ void csr_scan2(const int* __restrict__ bsum, int* __restrict__ boff) {
    __shared__ int wsum[8];
    int tid = threadIdx.x, lane = tid & 31, wid = tid >> 5;
    int v = (tid < NBLK) ? bsum[tid] : 0;
    int x = v;
    #pragma unroll
    for (int o = 1; o < 32; o <<= 1) {
        int t = __shfl_up_sync(FULL, x, o);
        if (lane >= o) x += t;
    }
    if (lane == 31) wsum[wid] = x;
    __syncthreads();
    if (wid == 0) {
        int w = (lane < 8) ? wsum[lane] : 0;
        #pragma unroll
        for (int o = 1; o < 8; o <<= 1) {
            int t = __shfl_up_sync(FULL, w, o);
            if (lane >= o) w += t;
        }
        if (lane < 8) wsum[lane] = w;
    }
    __syncthreads();
    int inc = x + (wid > 0 ? wsum[wid - 1] : 0);
    if (tid < NBLK) boff[tid] = inc - v;   // exclusive
}

__global__ void csr_scan3(const int* __restrict__ cnt, const int* __restrict__ incl,
                          const int* __restrict__ boff, int* __restrict__ rowptr,
                          int* __restrict__ cursor) {
    int b = blockIdx.x;
    int i = b * SB + threadIdx.x;
    if (i < NN) {
        int ex = incl[i] - cnt[i] + boff[b];
        rowptr[i] = ex;
        cursor[i] = ex;
    }
    if (i == 0) rowptr[NN] = NE;
}

__global__ void csr_fill(const int* __restrict__ src, const int* __restrict__ dst,
                         int* __restrict__ cursor, int* __restrict__ csrc) {
    int e = blockIdx.x * blockDim.x + threadIdx.x;
    if (e >= NE) return;
    int p = atomicAdd(&cursor[dst[e]], 1);
    csrc[p] = src[e];
}

// ============================ GEMM (+ el/er) ================================
// Block = 256 threads = 8 warps; each warp computes 4 rows x 64 cols.
// W staged in shared; x rows staged in shared; lane owns cols (2*lane, 2*lane+1).
template <int K>
__global__ void __launch_bounds__(256)
gemm_el_er(const float* __restrict__ x, const float* __restrict__ W,
           const float* __restrict__ al, const float* __restrict__ ar,
           float* __restrict__ h, float* __restrict__ el, float* __restrict__ er) {
    __shared__ float sW[K * HF];
    __shared__ float sx[32][K];

    int tid = threadIdx.x;
    int base = blockIdx.x * 32;

    for (int i = tid; i < K * HF; i += 256) sW[i] = W[i];
    for (int i = tid; i < 32 * K; i += 256) {
        int r = i / K, c = i % K;
        int row = base + r;
        sx[r][c] = (row < NN) ? x[row * K + c] : 0.0f;
    }
    __syncthreads();

    int warp = tid >> 5, lane = tid & 31;
    int c = 2 * lane;
    float alc0 = al[c], alc1 = al[c + 1];
    float arc0 = ar[c], arc1 = ar[c + 1];

    float acc[4][2];
    #pragma unroll
    for (int j = 0; j < 4; j++) { acc[j][0] = 0.0f; acc[j][1] = 0.0f; }

    int r0 = warp * 4;
    #pragma unroll 8
    for (int k = 0; k < K; k++) {
        float2 w2 = *(const float2*)&sW[k * HF + c];
        #pragma unroll
        for (int j = 0; j < 4; j++) {
            float xv = sx[r0 + j][k];
            acc[j][0] = fmaf(xv, w2.x, acc[j][0]);
            acc[j][1] = fmaf(xv, w2.y, acc[j][1]);
        }
    }

    #pragma unroll
    for (int j = 0; j < 4; j++) {
        int g = base + r0 + j;
        if (g >= NN) break;
        *(float2*)&h[g * HF + c] = make_float2(acc[j][0], acc[j][1]);
        float pel = acc[j][0] * alc0 + acc[j][1] * alc1;
        float per = acc[j][0] * arc0 + acc[j][1] * arc1;
        #pragma unroll
        for (int o = 16; o > 0; o >>= 1) {
            pel += __shfl_xor_sync(FULL, pel, o);
            per += __shfl_xor_sync(FULL, per, o);
        }
        if (lane == 0) { el[g] = pel; er[g] = per; }
    }
}

// ============== fused per-node softmax + aggregate + bias + relu ============
// One warp per dst node. Online softmax over groups of 32 incoming edges.
// Lane owns feature cols (2*lane, 2*lane+1).
__global__ void __launch_bounds__(256)
gat_aggregate(const int* __restrict__ rowptr, const int* __restrict__ csrc,
              const float* __restrict__ el, const float* __restrict__ er,
              const float* __restrict__ h, const float* __restrict__ b,
              float* __restrict__ y) {
    int gwarp = (blockIdx.x * blockDim.x + threadIdx.x) >> 5;
    if (gwarp >= NN) return;
    int lane = threadIdx.x & 31;

    int beg = rowptr[gwarp], end = rowptr[gwarp + 1];
    float erd = er[gwarp];

    float m = -__int_as_float(0x7F800000);   // -inf
    float s = 0.0f, acc0 = 0.0f, acc1 = 0.0f;

    for (int base = beg; base < end; base += 32) {
        int idx = base + lane;
        bool valid = idx < end;
        int sn = valid ? csrc[idx] : 0;
        float v;
        if (valid) {
            v = el[sn] + erd;
            v = v > 0.0f ? v : 0.2f * v;          // leaky relu
        } else {
            v = -__int_as_float(0x7F800000);
        }
        // group max
        float gm = v;
        #pragma unroll
        for (int o = 16; o > 0; o >>= 1)
            gm = fmaxf(gm, __shfl_xor_sync(FULL, gm, o));
        float mnew = fmaxf(m, gm);
        float scale = __expf(m - mnew);           // 0 on first group, else <=1
        s *= scale; acc0 *= scale; acc1 *= scale;
        m = mnew;

        float w = valid ? __expf(v - mnew) : 0.0f;
        float ws = w;
        #pragma unroll
        for (int o = 16; o > 0; o >>= 1)
            ws += __shfl_xor_sync(FULL, ws, o);
        s += ws;

        int cnt = end - base; if (cnt > 32) cnt = 32;
        #pragma unroll 4
        for (int j = 0; j < cnt; j++) {
            int   sj = __shfl_sync(FULL, sn, j);
            float wj = __shfl_sync(FULL, w,  j);
            float2 hv = *(const float2*)&h[sj * HF + 2 * lane];
            acc0 = fmaf(wj, hv.x, acc0);
            acc1 = fmaf(wj, hv.y, acc1);
        }
    }

    float inv = (end > beg) ? __fdividef(1.0f, s) : 0.0f;
    int c = 2 * lane;
    float o0 = acc0 * inv + b[c];
    float o1 = acc1 * inv + b[c + 1];
    o0 = o0 > 0.0f ? o0 : 0.0f;
    o1 = o1 > 0.0f ? o1 : 0.0f;
    *(float2*)&y[gwarp * HF + c] = make_float2(o0, o1);
}

// ============================ host driver ===================================
template <int K>
static void run_layer(const float* x, const float* W, const float* al,
                      const float* ar, const float* b,
                      const int* rowptr, const int* csrc,
                      float* h, float* el, float* er, float* y) {
    gemm_el_er<K><<<(NN + 31) / 32, 256>>>(x, W, al, ar, h, el, er);
    gat_aggregate<<<(NN * 32 + 255) / 256, 256>>>(rowptr, csrc, el, er, h, b, y);
}

extern "C" void kernel_launch(void* const* d_in, const int* in_sizes, int n_in,
                              void* d_out, int out_size) {
    const float* x   = (const float*)d_in[0];
    const int*   src = (const int*)  d_in[1];
    const int*   dst = (const int*)  d_in[2];
    const float* W1  = (const float*)d_in[3];
    const float* al1 = (const float*)d_in[4];
    const float* ar1 = (const float*)d_in[5];
    const float* b1  = (const float*)d_in[6];
    const float* W2  = (const float*)d_in[7];
    const float* al2 = (const float*)d_in[8];
    const float* ar2 = (const float*)d_in[9];
    const float* b2  = (const float*)d_in[10];
    const float* W3  = (const float*)d_in[11];
    const float* al3 = (const float*)d_in[12];
    const float* ar3 = (const float*)d_in[13];
    const float* b3  = (const float*)d_in[14];
    float* out = (float*)d_out;

    float *h, *nf, *nf2, *el, *er;
    int *cnt, *incl, *bsum, *boff, *rowptr, *cursor, *csrc;
    cudaGetSymbolAddress((void**)&h,      g_h);
    cudaGetSymbolAddress((void**)&nf,     g_nf);
    cudaGetSymbolAddress((void**)&nf2,    g_nf2);
    cudaGetSymbolAddress((void**)&el,     g_el);
    cudaGetSymbolAddress((void**)&er,     g_er);
    cudaGetSymbolAddress((void**)&cnt,    g_cnt);
    cudaGetSymbolAddress((void**)&incl,   g_incl);
    cudaGetSymbolAddress((void**)&bsum,   g_bsum);
    cudaGetSymbolAddress((void**)&boff,   g_boff);
    cudaGetSymbolAddress((void**)&rowptr, g_rowptr);
    cudaGetSymbolAddress((void**)&cursor, g_cursor);
    cudaGetSymbolAddress((void**)&csrc,   g_csrc);

    // ---- CSR by dst (once; reused by all 3 layers) ----
    csr_zero<<<(NN + 255) / 256, 256>>>(cnt);
    csr_hist<<<(NE + 255) / 256, 256>>>(dst, cnt);
    csr_scan1<<<NBLK, SB>>>(cnt, incl, bsum);
    csr_scan2<<<1, 256>>>(bsum, boff);
    csr_scan3<<<NBLK, SB>>>(cnt, incl, boff, rowptr, cursor);
    csr_fill<<<(NE + 255) / 256, 256>>>(src, dst, cursor, csrc);

    // ---- 3 GAT layers ----
    run_layer<128>(x,   W1, al1, ar1, b1, rowptr, csrc, h, el, er, nf);
    run_layer<64>(nf,  W2, al2, ar2, b2, rowptr, csrc, h, el, er, nf2);
    run_layer<64>(nf2, W3, al3, ar3, b3, rowptr, csrc, h, el, er, out);
}

// round 4
// speedup vs baseline: 3.8825x; 1.3543x over previous
#include <cuda_runtime.h>
#include <cuda_bf16.h>

#define NN 100000
#define NE 1600000
#define HF 64
#define FULL 0xFFFFFFFFu

#define SB   512
#define NBLK ((NN + SB - 1) / SB)   // 196

// ---------------- scratch (device globals; no allocation allowed) ----------
__device__ float g_h  [NN * HF];
__device__ float g_nf [NN * HF];
__device__ float g_nf2[NN * HF];
__device__ float g_el [NN];
__device__ float g_er [NN];
// CSR-by-dst
__device__ int g_cnt   [NN];
__device__ int g_incl  [NN];
__device__ int g_bsum  [NBLK];
__device__ int g_boff  [NBLK];
__device__ int g_rowptr[NN + 1];
__device__ int g_cursor[NN];
__device__ int g_csrc  [NE];

// ============================ CSR build =====================================
__global__ void csr_zero(int* __restrict__ cnt) {
    int i = blockIdx.x * blockDim.x + threadIdx.x;
    if (i < NN) cnt[i] = 0;
}

__global__ void csr_hist(const int* __restrict__ dst, int* __restrict__ cnt) {
    int e = blockIdx.x * blockDim.x + threadIdx.x;
    if (e < NE) atomicAdd(&cnt[dst[e]], 1);
}

__global__ void csr_scan1(const int* __restrict__ cnt, int* __restrict__ incl,
                          int* __restrict__ bsum) {
    __shared__ int wsum[16];
    int tid = threadIdx.x, lane = tid & 31, wid = tid >> 5;
    int i = blockIdx.x * SB + tid;
    int v = (i < NN) ? cnt[i] : 0;
    int x = v;
    #pragma unroll
    for (int o = 1; o < 32; o <<= 1) {
        int t = __shfl_up_sync(FULL, x, o);
        if (lane >= o) x += t;
    }
    if (lane == 31) wsum[wid] = x;
    __syncthreads();
    if (wid == 0) {
        int w = (lane < 16) ? wsum[lane] : 0;
        #pragma unroll
        for (int o = 1; o < 16; o <<= 1) {
            int t = __shfl_up_sync(FULL, w, o);
            if (lane >= o) w += t;
        }
        if (lane < 16) wsum[lane] = w;
    }
    __syncthreads();
    int inc = x + (wid > 0 ? wsum[wid - 1] : 0);
    if (i < NN) incl[i] = inc;
    if (tid == SB - 1) bsum[blockIdx.x] = inc;
}

__global__ void csr_scan2(const int* __restrict__ bsum, int* __restrict__ boff) {
    __shared__ int wsum[8];
    int tid = threadIdx.x, lane = tid & 31, wid = tid >> 5;
    int v = (tid < NBLK) ? bsum[tid] : 0;
    int x = v;
    #pragma unroll
    for (int o = 1; o < 32; o <<= 1) {
        int t = __shfl_up_sync(FULL, x, o);
        if (lane >= o) x += t;
    }
    if (lane == 31) wsum[wid] = x;
    __syncthreads();
    if (wid == 0) {
        int w = (lane < 8) ? wsum[lane] : 0;
        #pragma unroll
        for (int o = 1; o < 8; o <<= 1) {
            int t = __shfl_up_sync(FULL, w, o);
            if (lane >= o) w += t;
        }
        if (lane < 8) wsum[lane] = w;
    }
    __syncthreads();
    int inc = x + (wid > 0 ? wsum[wid - 1] : 0);
    if (tid < NBLK) boff[tid] = inc - v;
}

__global__ void csr_scan3(const int* __restrict__ cnt, const int* __restrict__ incl,
                          const int* __restrict__ boff, int* __restrict__ rowptr,
                          int* __restrict__ cursor) {
    int b = blockIdx.x;
    int i = b * SB + threadIdx.x;
    if (i < NN) {
        int ex = incl[i] - cnt[i] + boff[b];
        rowptr[i] = ex;
        cursor[i] = ex;
    }
    if (i == 0) rowptr[NN] = NE;
}

__global__ void csr_fill(const int* __restrict__ src, const int* __restrict__ dst,
                         int* __restrict__ cursor, int* __restrict__ csrc) {
    int e = blockIdx.x * blockDim.x + threadIdx.x;
    if (e >= NE) return;
    int p = atomicAdd(&cursor[dst[e]], 1);
    csrc[p] = src[e];
}

// ============================ GEMM (+ el/er) ================================
// 64x64 output tile per 256-thread block; each thread computes a 4x4 subtile.
// K processed in chunks of 64. Per k-step: 1 LDS.128 (W) + 4 LDS (x) -> 16 FMA.
template <int K>
__global__ void __launch_bounds__(256)
gemm_el_er(const float* __restrict__ x, const float* __restrict__ W,
           const float* __restrict__ al, const float* __restrict__ ar,
           float* __restrict__ h, float* __restrict__ el, float* __restrict__ er) {
    __shared__ float sx[64][68];   // pad 68: float4-aligned rows, conflict-free
    __shared__ float sW[64][64];

    int tid = threadIdx.x;
    int base = blockIdx.x * 64;
    int tx = tid & 15, ty = tid >> 4;
    int c0 = tx * 4, r0 = ty * 4;

    float acc[4][4];
    #pragma unroll
    for (int j = 0; j < 4; j++)
        #pragma unroll
        for (int q = 0; q < 4; q++) acc[j][q] = 0.0f;

    for (int kc = 0; kc < K; kc += 64) {
        if (kc) __syncthreads();
        #pragma unroll
        for (int i = tid; i < 64 * 16; i += 256) {
            int r = i >> 4, q = i & 15;
            int row = base + r;
            float4 v = make_float4(0.f, 0.f, 0.f, 0.f);
            if (row < NN) v = *(const float4*)&x[row * K + kc + q * 4];
            *(float4*)&sx[r][q * 4] = v;
        }
        #pragma unroll
        for (int i = tid; i < 64 * 16; i += 256) {
            int k = i >> 4, q = i & 15;
            *(float4*)&sW[k][q * 4] = *(const float4*)&W[(kc + k) * HF + q * 4];
        }
        __syncthreads();

        #pragma unroll 4
        for (int k = 0; k < 64; k++) {
            float4 w4 = *(const float4*)&sW[k][c0];
            #pragma unroll
            for (int j = 0; j < 4; j++) {
                float xv = sx[r0 + j][k];
                acc[j][0] = fmaf(xv, w4.x, acc[j][0]);
                acc[j][1] = fmaf(xv, w4.y, acc[j][1]);
                acc[j][2] = fmaf(xv, w4.z, acc[j][2]);
                acc[j][3] = fmaf(xv, w4.w, acc[j][3]);
            }
        }
    }

    float4 al4 = *(const float4*)&al[c0];
    float4 ar4 = *(const float4*)&ar[c0];
    #pragma unroll
    for (int j = 0; j < 4; j++) {
        int g = base + r0 + j;
        bool ok = g < NN;
        if (ok) *(float4*)&h[g * HF + c0] =
            make_float4(acc[j][0], acc[j][1], acc[j][2], acc[j][3]);
        float pel = acc[j][0] * al4.x + acc[j][1] * al4.y
                  + acc[j][2] * al4.z + acc[j][3] * al4.w;
        float per = acc[j][0] * ar4.x + acc[j][1] * ar4.y
                  + acc[j][2] * ar4.z + acc[j][3] * ar4.w;
        #pragma unroll
        for (int o = 8; o > 0; o >>= 1) {   // reduce across the 16 tx lanes
            pel += __shfl_xor_sync(FULL, pel, o);
            per += __shfl_xor_sync(FULL, per, o);
        }
        if (tx == 0 && ok) { el[g] = pel; er[g] = per; }
    }
}

// ============== fused per-node softmax + aggregate + bias + relu ============
__global__ void __launch_bounds__(256)
gat_aggregate(const int* __restrict__ rowptr, const int* __restrict__ csrc,
              const float* __restrict__ el, const float* __restrict__ er,
              const float* __restrict__ h, const float* __restrict__ b,
              float* __restrict__ y) {
    int gwarp = (blockIdx.x * blockDim.x + threadIdx.x) >> 5;
    if (gwarp >= NN) return;
    int lane = threadIdx.x & 31;

    int beg = rowptr[gwarp], end = rowptr[gwarp + 1];
    float erd = er[gwarp];

    float m = -__int_as_float(0x7F800000);
    float s = 0.0f, acc0 = 0.0f, acc1 = 0.0f;

    for (int base = beg; base < end; base += 32) {
        int idx = base + lane;
        bool valid = idx < end;
        int sn = valid ? csrc[idx] : 0;
        float v;
        if (valid) {
            v = el[sn] + erd;
            v = v > 0.0f ? v : 0.2f * v;
        } else {
            v = -__int_as_float(0x7F800000);
        }
        float gm = v;
        #pragma unroll
        for (int o = 16; o > 0; o >>= 1)
            gm = fmaxf(gm, __shfl_xor_sync(FULL, gm, o));
        float mnew = fmaxf(m, gm);
        float scale = __expf(m - mnew);
        s *= scale; acc0 *= scale; acc1 *= scale;
        m = mnew;

        float w = valid ? __expf(v - mnew) : 0.0f;
        float ws = w;
        #pragma unroll
        for (int o = 16; o > 0; o >>= 1)
            ws += __shfl_xor_sync(FULL, ws, o);
        s += ws;

        int cnt = end - base; if (cnt > 32) cnt = 32;
        #pragma unroll 4
        for (int j = 0; j < cnt; j++) {
            int   sj = __shfl_sync(FULL, sn, j);
            float wj = __shfl_sync(FULL, w,  j);
            float2 hv = *(const float2*)&h[sj * HF + 2 * lane];
            acc0 = fmaf(wj, hv.x, acc0);
            acc1 = fmaf(wj, hv.y, acc1);
        }
    }

    float inv = (end > beg) ? __fdividef(1.0f, s) : 0.0f;
    int c = 2 * lane;
    float o0 = acc0 * inv + b[c];
    float o1 = acc1 * inv + b[c + 1];
    o0 = o0 > 0.0f ? o0 : 0.0f;
    o1 = o1 > 0.0f ? o1 : 0.0f;
    *(float2*)&y[gwarp * HF + c] = make_float2(o0, o1);
}

// ============================ host driver ===================================
extern "C" void kernel_launch(void* const* d_in, const int* in_sizes, int n_in,
                              void* d_out, int out_size) {
    const float* x   = (const float*)d_in[0];
    const int*   src = (const int*)  d_in[1];
    const int*   dst = (const int*)  d_in[2];
    const float* W1  = (const float*)d_in[3];
    const float* al1 = (const float*)d_in[4];
    const float* ar1 = (const float*)d_in[5];
    const float* b1  = (const float*)d_in[6];
    const float* W2  = (const float*)d_in[7];
    const float* al2 = (const float*)d_in[8];
    const float* ar2 = (const float*)d_in[9];
    const float* b2  = (const float*)d_in[10];
    const float* W3  = (const float*)d_in[11];
    const float* al3 = (const float*)d_in[12];
    const float* ar3 = (const float*)d_in[13];
    const float* b3  = (const float*)d_in[14];
    float* out = (float*)d_out;

    float *h, *nf, *nf2, *el, *er;
    int *cnt, *incl, *bsum, *boff, *rowptr, *cursor, *csrc;
    cudaGetSymbolAddress((void**)&h,      g_h);
    cudaGetSymbolAddress((void**)&nf,     g_nf);
    cudaGetSymbolAddress((void**)&nf2,    g_nf2);
    cudaGetSymbolAddress((void**)&el,     g_el);
    cudaGetSymbolAddress((void**)&er,     g_er);
    cudaGetSymbolAddress((void**)&cnt,    g_cnt);
    cudaGetSymbolAddress((void**)&incl,   g_incl);
    cudaGetSymbolAddress((void**)&bsum,   g_bsum);
    cudaGetSymbolAddress((void**)&boff,   g_boff);
    cudaGetSymbolAddress((void**)&rowptr, g_rowptr);
    cudaGetSymbolAddress((void**)&cursor, g_cursor);
    cudaGetSymbolAddress((void**)&csrc,   g_csrc);

    // side stream + events, created once on the first (uncaptured) call
    static cudaStream_t s2 = nullptr;
    static cudaEvent_t evFork = nullptr, evJoin = nullptr;
    if (!s2) {
        cudaStreamCreateWithFlags(&s2, cudaStreamNonBlocking);
        cudaEventCreateWithFlags(&evFork, cudaEventDisableTiming);
        cudaEventCreateWithFlags(&evJoin, cudaEventDisableTiming);
    }

    // ---- fork: CSR build on s2, layer-1 GEMM on main stream ----
    cudaEventRecord(evFork, 0);
    cudaStreamWaitEvent(s2, evFork, 0);
    csr_zero<<<(NN + 255) / 256, 256, 0, s2>>>(cnt);
    csr_hist<<<(NE + 255) / 256, 256, 0, s2>>>(dst, cnt);
    csr_scan1<<<NBLK, SB, 0, s2>>>(cnt, incl, bsum);
    csr_scan2<<<1, 256, 0, s2>>>(bsum, boff);
    csr_scan3<<<NBLK, SB, 0, s2>>>(cnt, incl, boff, rowptr, cursor);
    csr_fill<<<(NE + 255) / 256, 256, 0, s2>>>(src, dst, cursor, csrc);
    cudaEventRecord(evJoin, s2);

    gemm_el_er<128><<<(NN + 63) / 64, 256>>>(x, W1, al1, ar1, h, el, er);

    cudaStreamWaitEvent(0, evJoin, 0);   // join before aggregate needs CSR

    // ---- layer 1 aggregate, then layers 2 & 3 ----
    gat_aggregate<<<(NN * 32 + 255) / 256, 256>>>(rowptr, csrc, el, er, h, b1, nf);

    gemm_el_er<64><<<(NN + 63) / 64, 256>>>(nf, W2, al2, ar2, h, el, er);
    gat_aggregate<<<(NN * 32 + 255) / 256, 256>>>(rowptr, csrc, el, er, h, b2, nf2);

    gemm_el_er<64><<<(NN + 63) / 64, 256>>>(nf2, W3, al3, ar3, h, el, er);
    gat_aggregate<<<(NN * 32 + 255) / 256, 256>>>(rowptr, csrc, el, er, h, b3, out);
}